// round 1
// baseline (speedup 1.0000x reference)
#include <cuda_runtime.h>
#include <math.h>

#define SEQ 2048
#define DM 2048
#define NH 16
#define HD 128
#define QKVN (3*DM)

// Scratch (allocation-free rule: __device__ globals)
__device__ float g_qkv[SEQ * QKVN];     // [S, 3D]
__device__ float g_q[NH * SEQ * HD];    // [H, S, HD]
__device__ float g_k[NH * SEQ * HD];
__device__ float g_v[NH * SEQ * HD];
__device__ float g_ctx[SEQ * DM];       // [S, D]

// ---------------------------------------------------------------------------
// SGEMM: C[M,N] = A[M,K] @ B[K,N] + bias[N]
// 128x128 block, BK=16, 256 threads, 8x8 per-thread tile, double-buffered smem
// ---------------------------------------------------------------------------
__global__ __launch_bounds__(256, 2)
void sgemm_bias_kernel(const float* __restrict__ A, const float* __restrict__ B,
                       const float* __restrict__ bias, float* __restrict__ C,
                       int M, int N, int K)
{
    __shared__ float As[2][16][132];   // transposed A tile: As[k][m], padded
    __shared__ float Bs[2][16][128];   // Bs[k][n]

    const int tid = threadIdx.x;
    const int bx = blockIdx.x, by = blockIdx.y;
    const int ty = tid >> 4, tx = tid & 15;

    const int arow = tid >> 2;          // 0..63
    const int acol = (tid & 3) << 2;    // 0,4,8,12
    const int brow = tid >> 5;          // 0..7
    const int bcol = (tid & 31) << 2;   // 0..124

    const float* Ap = A + (size_t)(by * 128 + arow) * K + acol;
    const float* Bp = B + (size_t)brow * N + bx * 128 + bcol;

    float acc[8][8];
#pragma unroll
    for (int i = 0; i < 8; ++i)
#pragma unroll
        for (int j = 0; j < 8; ++j) acc[i][j] = 0.f;

    float4 a0 = *(const float4*)(Ap);
    float4 a1 = *(const float4*)(Ap + (size_t)64 * K);
    float4 b0 = *(const float4*)(Bp);
    float4 b1 = *(const float4*)(Bp + (size_t)8 * N);

    As[0][acol+0][arow] = a0.x; As[0][acol+1][arow] = a0.y;
    As[0][acol+2][arow] = a0.z; As[0][acol+3][arow] = a0.w;
    As[0][acol+0][arow+64] = a1.x; As[0][acol+1][arow+64] = a1.y;
    As[0][acol+2][arow+64] = a1.z; As[0][acol+3][arow+64] = a1.w;
    *(float4*)&Bs[0][brow][bcol] = b0;
    *(float4*)&Bs[0][brow+8][bcol] = b1;
    __syncthreads();

    const int nt = K >> 4;
    int buf = 0;
    for (int kt = 0; kt < nt; ++kt) {
        if (kt + 1 < nt) {   // prefetch next tile into registers
            const float* Ap2 = Ap + (kt + 1) * 16;
            const float* Bp2 = Bp + (size_t)(kt + 1) * 16 * N;
            a0 = *(const float4*)(Ap2);
            a1 = *(const float4*)(Ap2 + (size_t)64 * K);
            b0 = *(const float4*)(Bp2);
            b1 = *(const float4*)(Bp2 + (size_t)8 * N);
        }
#pragma unroll
        for (int k = 0; k < 16; ++k) {
            float4 ra0 = *(const float4*)&As[buf][k][ty * 8];
            float4 ra1 = *(const float4*)&As[buf][k][ty * 8 + 4];
            float4 rb0 = *(const float4*)&Bs[buf][k][tx * 8];
            float4 rb1 = *(const float4*)&Bs[buf][k][tx * 8 + 4];
            float av[8] = {ra0.x, ra0.y, ra0.z, ra0.w, ra1.x, ra1.y, ra1.z, ra1.w};
            float bv[8] = {rb0.x, rb0.y, rb0.z, rb0.w, rb1.x, rb1.y, rb1.z, rb1.w};
#pragma unroll
            for (int i = 0; i < 8; ++i)
#pragma unroll
                for (int j = 0; j < 8; ++j)
                    acc[i][j] = fmaf(av[i], bv[j], acc[i][j]);
        }
        if (kt + 1 < nt) {
            const int nb = buf ^ 1;
            As[nb][acol+0][arow] = a0.x; As[nb][acol+1][arow] = a0.y;
            As[nb][acol+2][arow] = a0.z; As[nb][acol+3][arow] = a0.w;
            As[nb][acol+0][arow+64] = a1.x; As[nb][acol+1][arow+64] = a1.y;
            As[nb][acol+2][arow+64] = a1.z; As[nb][acol+3][arow+64] = a1.w;
            *(float4*)&Bs[nb][brow][bcol] = b0;
            *(float4*)&Bs[nb][brow+8][bcol] = b1;
            __syncthreads();
            buf = nb;
        }
    }

    const int crow = by * 128 + ty * 8;
    const int ccol = bx * 128 + tx * 8;
    float4 bz0 = *(const float4*)&bias[ccol];
    float4 bz1 = *(const float4*)&bias[ccol + 4];
#pragma unroll
    for (int i = 0; i < 8; ++i) {
        float4 o0 = make_float4(acc[i][0] + bz0.x, acc[i][1] + bz0.y,
                                acc[i][2] + bz0.z, acc[i][3] + bz0.w);
        float4 o1 = make_float4(acc[i][4] + bz1.x, acc[i][5] + bz1.y,
                                acc[i][6] + bz1.z, acc[i][7] + bz1.w);
        float* cp = C + (size_t)(crow + i) * N + ccol;
        *(float4*)cp = o0;
        *(float4*)(cp + 4) = o1;
    }
}

// ---------------------------------------------------------------------------
// RoPE + split/scatter qkv -> Q,K,V in [H, S, HD] layout. Q pre-scaled by
// HD^-0.5 so attention skips the score scale.
// ---------------------------------------------------------------------------
__global__ void rope_scatter_kernel(const float* __restrict__ fc)
{
    int idx = blockIdx.x * blockDim.x + threadIdx.x;
    const int total = SEQ * NH * (HD / 2);
    if (idx >= total) return;
    int i = idx & 63;            // pair index within head (HD/2 = 64)
    int h = (idx >> 6) & 15;
    int s = idx >> 10;
    float c  = fc[(s * 64 + i) * 2 + 0];
    float sn = fc[(s * 64 + i) * 2 + 1];
    const float* row = g_qkv + (size_t)s * QKVN;
    int d = h * HD + 2 * i;
    float q0 = row[d],           q1 = row[d + 1];
    float k0 = row[DM + d],      k1 = row[DM + d + 1];
    float v0 = row[2 * DM + d],  v1 = row[2 * DM + d + 1];
    const float qs = 0.08838834764831845f;   // 128^-0.5
    size_t o = ((size_t)h * SEQ + s) * HD + 2 * i;
    g_q[o]     = (q0 * c - q1 * sn) * qs;
    g_q[o + 1] = (q1 * c + q0 * sn) * qs;
    g_k[o]     = k0 * c - k1 * sn;
    g_k[o + 1] = k1 * c + k0 * sn;
    g_v[o]     = v0;
    g_v[o + 1] = v1;
}

// ---------------------------------------------------------------------------
// Flash attention, fp32, causal. BM=128 q rows per CTA, BN=64 kv per iter.
// 256 threads = 16x16 grid; score tile 8x4/thread, output tile 8x8/thread.
// ---------------------------------------------------------------------------
#define FLASH_SMEM ((128*132 + 64*132 + 64*132 + 128*68) * 4)

__global__ __launch_bounds__(256, 1)
void flash_attn_kernel()
{
    extern __shared__ float smf[];
    float* Qs = smf;                    // 128 x 132 (padded)
    float* Ks = Qs + 128 * 132;         // 64 x 132
    float* Vs = Ks + 64 * 132;          // 64 x 132
    float* Ps = Vs + 64 * 132;          // 128 x 68

    const int h  = blockIdx.y;
    const int qt = gridDim.x - 1 - blockIdx.x;   // longest tiles launch first
    const int tid = threadIdx.x;
    const int ty = tid >> 4, tx = tid & 15;

    const float* Qh = g_q + (size_t)h * SEQ * HD;
    const float* Kh = g_k + (size_t)h * SEQ * HD;
    const float* Vh = g_v + (size_t)h * SEQ * HD;

    // load Q tile (scaled already)
#pragma unroll
    for (int t = 0; t < 16; ++t) {
        int idx = tid + t * 256;                 // 128 rows * 32 float4
        int r = idx >> 5, c4 = (idx & 31) << 2;
        *(float4*)&Qs[r * 132 + c4] =
            *(const float4*)&Qh[((size_t)(qt * 128 + r)) * HD + c4];
    }

    float O[8][8];
    float m[8], l[8];
#pragma unroll
    for (int i = 0; i < 8; ++i) {
        m[i] = -1e30f; l[i] = 0.f;
#pragma unroll
        for (int j = 0; j < 8; ++j) O[i][j] = 0.f;
    }

    const int jmax = 2 * qt + 1;
    for (int j = 0; j <= jmax; ++j) {
        __syncthreads();   // protect Ks/Vs/Ps from previous-iter readers
#pragma unroll
        for (int t = 0; t < 8; ++t) {
            int idx = tid + t * 256;             // 64 rows * 32 float4
            int r = idx >> 5, c4 = (idx & 31) << 2;
            size_t g = ((size_t)(j * 64 + r)) * HD + c4;
            *(float4*)&Ks[r * 132 + c4] = *(const float4*)&Kh[g];
            *(float4*)&Vs[r * 132 + c4] = *(const float4*)&Vh[g];
        }
        __syncthreads();

        // S = Q K^T  (8x4 per thread over 128-dim)
        float sc[8][4];
#pragma unroll
        for (int i = 0; i < 8; ++i)
#pragma unroll
            for (int c = 0; c < 4; ++c) sc[i][c] = 0.f;

        for (int k = 0; k < 128; k += 4) {
            float4 kv[4];
#pragma unroll
            for (int c = 0; c < 4; ++c)
                kv[c] = *(const float4*)&Ks[(tx * 4 + c) * 132 + k];
#pragma unroll
            for (int i = 0; i < 8; ++i) {
                float4 qv = *(const float4*)&Qs[(ty * 8 + i) * 132 + k];
#pragma unroll
                for (int c = 0; c < 4; ++c) {
                    sc[i][c] = fmaf(qv.x, kv[c].x, sc[i][c]);
                    sc[i][c] = fmaf(qv.y, kv[c].y, sc[i][c]);
                    sc[i][c] = fmaf(qv.z, kv[c].z, sc[i][c]);
                    sc[i][c] = fmaf(qv.w, kv[c].w, sc[i][c]);
                }
            }
        }

        // causal mask (only the two diagonal-adjacent tiles need it)
        if (j * 64 + 63 > qt * 128) {
            const int qrow = qt * 128 + ty * 8;
            const int kcol = j * 64 + tx * 4;
#pragma unroll
            for (int i = 0; i < 8; ++i)
#pragma unroll
                for (int c = 0; c < 4; ++c)
                    if (kcol + c > qrow + i) sc[i][c] = -1e30f;
        }

        // online softmax update; row owned by the 16 threads sharing ty
#pragma unroll
        for (int i = 0; i < 8; ++i) {
            float tm = fmaxf(fmaxf(sc[i][0], sc[i][1]), fmaxf(sc[i][2], sc[i][3]));
            tm = fmaxf(tm, __shfl_xor_sync(0xffffffffu, tm, 1));
            tm = fmaxf(tm, __shfl_xor_sync(0xffffffffu, tm, 2));
            tm = fmaxf(tm, __shfl_xor_sync(0xffffffffu, tm, 4));
            tm = fmaxf(tm, __shfl_xor_sync(0xffffffffu, tm, 8));
            float mn = fmaxf(m[i], tm);
            float al = __expf(m[i] - mn);
            float rs = 0.f;
#pragma unroll
            for (int c = 0; c < 4; ++c) {
                float p = __expf(sc[i][c] - mn);
                sc[i][c] = p;
                rs += p;
            }
            rs += __shfl_xor_sync(0xffffffffu, rs, 1);
            rs += __shfl_xor_sync(0xffffffffu, rs, 2);
            rs += __shfl_xor_sync(0xffffffffu, rs, 4);
            rs += __shfl_xor_sync(0xffffffffu, rs, 8);
            l[i] = l[i] * al + rs;
            m[i] = mn;
#pragma unroll
            for (int jj = 0; jj < 8; ++jj) O[i][jj] *= al;
            *(float4*)&Ps[(ty * 8 + i) * 68 + tx * 4] =
                make_float4(sc[i][0], sc[i][1], sc[i][2], sc[i][3]);
        }
        __syncthreads();

        // O += P @ V  (8x8 per thread over 64-dim)
        for (int k = 0; k < 64; k += 4) {
            float4 pv[8];
#pragma unroll
            for (int i = 0; i < 8; ++i)
                pv[i] = *(const float4*)&Ps[(ty * 8 + i) * 68 + k];
#pragma unroll
            for (int kk = 0; kk < 4; ++kk) {
                float4 va = *(const float4*)&Vs[(k + kk) * 132 + tx * 8];
                float4 vb = *(const float4*)&Vs[(k + kk) * 132 + tx * 8 + 4];
#pragma unroll
                for (int i = 0; i < 8; ++i) {
                    float p = (kk == 0) ? pv[i].x : (kk == 1) ? pv[i].y
                            : (kk == 2) ? pv[i].z : pv[i].w;
                    O[i][0] = fmaf(p, va.x, O[i][0]);
                    O[i][1] = fmaf(p, va.y, O[i][1]);
                    O[i][2] = fmaf(p, va.z, O[i][2]);
                    O[i][3] = fmaf(p, va.w, O[i][3]);
                    O[i][4] = fmaf(p, vb.x, O[i][4]);
                    O[i][5] = fmaf(p, vb.y, O[i][5]);
                    O[i][6] = fmaf(p, vb.z, O[i][6]);
                    O[i][7] = fmaf(p, vb.w, O[i][7]);
                }
            }
        }
    }

    // normalize and write ctx in [S, D] layout (head h occupies cols h*128..)
#pragma unroll
    for (int i = 0; i < 8; ++i) {
        float inv = 1.f / l[i];
        int row = qt * 128 + ty * 8 + i;
        float* cp = g_ctx + (size_t)row * DM + h * HD + tx * 8;
        *(float4*)cp       = make_float4(O[i][0]*inv, O[i][1]*inv, O[i][2]*inv, O[i][3]*inv);
        *(float4*)(cp + 4) = make_float4(O[i][4]*inv, O[i][5]*inv, O[i][6]*inv, O[i][7]*inv);
    }
}

// ---------------------------------------------------------------------------
extern "C" void kernel_launch(void* const* d_in, const int* in_sizes, int n_in,
                              void* d_out, int out_size)
{
    const float* x    = (const float*)d_in[0];
    const float* fc   = (const float*)d_in[1];
    // d_in[2] = input_pos (arange -> identity scatter, unused)
    const float* Wqkv = (const float*)d_in[3];
    const float* bqkv = (const float*)d_in[4];
    const float* Wd   = (const float*)d_in[5];
    const float* bd   = (const float*)d_in[6];
    float* out = (float*)d_out;

    float *qkv_p, *ctx_p;
    cudaGetSymbolAddress((void**)&qkv_p, g_qkv);
    cudaGetSymbolAddress((void**)&ctx_p, g_ctx);

    // 1) fused QKV projection: [S,D] @ [D,3D] + bias
    sgemm_bias_kernel<<<dim3(QKVN / 128, SEQ / 128), 256>>>(
        x, Wqkv, bqkv, qkv_p, SEQ, QKVN, DM);

    // 2) RoPE + split into [H,S,HD] Q/K/V (Q pre-scaled)
    rope_scatter_kernel<<<(SEQ * NH * (HD / 2) + 255) / 256, 256>>>(fc);

    // 3) causal flash attention
    cudaFuncSetAttribute(flash_attn_kernel,
                         cudaFuncAttributeMaxDynamicSharedMemorySize, FLASH_SMEM);
    flash_attn_kernel<<<dim3(SEQ / 128, NH), 256, FLASH_SMEM>>>();

    // 4) output projection: ctx @ Wdense + bias
    sgemm_bias_kernel<<<dim3(DM / 128, SEQ / 128), 256>>>(
        ctx_p, Wd, bd, out, SEQ, DM, DM);
}

// round 4
// speedup vs baseline: 1.3796x; 1.3796x over previous
#include <cuda_runtime.h>
#include <cuda_bf16.h>
#include <math.h>
#include <stdint.h>

#define SEQ 2048
#define DM 2048
#define NH 16
#define HD 128
#define QKVN (3*DM)

// Scratch (allocation-free rule: __device__ globals)
__device__ float g_qkv[SEQ * QKVN];     // [S, 3D]
__device__ float g_ctx[SEQ * DM];       // [S, D]
// bf16 hi/lo split copies for tensor-core attention, [H][S][HD]
__device__ __nv_bfloat16 g_qh[NH*SEQ*HD], g_ql[NH*SEQ*HD];
__device__ __nv_bfloat16 g_kh[NH*SEQ*HD], g_kl[NH*SEQ*HD];
__device__ __nv_bfloat16 g_vh[NH*SEQ*HD], g_vl[NH*SEQ*HD];

// ---------------------------------------------------------------------------
// SGEMM: C[M,N] = A[M,K] @ B[K,N] + bias[N]  (unchanged from R1)
// ---------------------------------------------------------------------------
__global__ __launch_bounds__(256, 2)
void sgemm_bias_kernel(const float* __restrict__ A, const float* __restrict__ B,
                       const float* __restrict__ bias, float* __restrict__ C,
                       int M, int N, int K)
{
    __shared__ float As[2][16][132];
    __shared__ float Bs[2][16][128];

    const int tid = threadIdx.x;
    const int bx = blockIdx.x, by = blockIdx.y;
    const int ty = tid >> 4, tx = tid & 15;

    const int arow = tid >> 2;
    const int acol = (tid & 3) << 2;
    const int brow = tid >> 5;
    const int bcol = (tid & 31) << 2;

    const float* Ap = A + (size_t)(by * 128 + arow) * K + acol;
    const float* Bp = B + (size_t)brow * N + bx * 128 + bcol;

    float acc[8][8];
#pragma unroll
    for (int i = 0; i < 8; ++i)
#pragma unroll
        for (int j = 0; j < 8; ++j) acc[i][j] = 0.f;

    float4 a0 = *(const float4*)(Ap);
    float4 a1 = *(const float4*)(Ap + (size_t)64 * K);
    float4 b0 = *(const float4*)(Bp);
    float4 b1 = *(const float4*)(Bp + (size_t)8 * N);

    As[0][acol+0][arow] = a0.x; As[0][acol+1][arow] = a0.y;
    As[0][acol+2][arow] = a0.z; As[0][acol+3][arow] = a0.w;
    As[0][acol+0][arow+64] = a1.x; As[0][acol+1][arow+64] = a1.y;
    As[0][acol+2][arow+64] = a1.z; As[0][acol+3][arow+64] = a1.w;
    *(float4*)&Bs[0][brow][bcol] = b0;
    *(float4*)&Bs[0][brow+8][bcol] = b1;
    __syncthreads();

    const int nt = K >> 4;
    int buf = 0;
    for (int kt = 0; kt < nt; ++kt) {
        if (kt + 1 < nt) {
            const float* Ap2 = Ap + (kt + 1) * 16;
            const float* Bp2 = Bp + (size_t)(kt + 1) * 16 * N;
            a0 = *(const float4*)(Ap2);
            a1 = *(const float4*)(Ap2 + (size_t)64 * K);
            b0 = *(const float4*)(Bp2);
            b1 = *(const float4*)(Bp2 + (size_t)8 * N);
        }
#pragma unroll
        for (int k = 0; k < 16; ++k) {
            float4 ra0 = *(const float4*)&As[buf][k][ty * 8];
            float4 ra1 = *(const float4*)&As[buf][k][ty * 8 + 4];
            float4 rb0 = *(const float4*)&Bs[buf][k][tx * 8];
            float4 rb1 = *(const float4*)&Bs[buf][k][tx * 8 + 4];
            float av[8] = {ra0.x, ra0.y, ra0.z, ra0.w, ra1.x, ra1.y, ra1.z, ra1.w};
            float bv[8] = {rb0.x, rb0.y, rb0.z, rb0.w, rb1.x, rb1.y, rb1.z, rb1.w};
#pragma unroll
            for (int i = 0; i < 8; ++i)
#pragma unroll
                for (int j = 0; j < 8; ++j)
                    acc[i][j] = fmaf(av[i], bv[j], acc[i][j]);
        }
        if (kt + 1 < nt) {
            const int nb = buf ^ 1;
            As[nb][acol+0][arow] = a0.x; As[nb][acol+1][arow] = a0.y;
            As[nb][acol+2][arow] = a0.z; As[nb][acol+3][arow] = a0.w;
            As[nb][acol+0][arow+64] = a1.x; As[nb][acol+1][arow+64] = a1.y;
            As[nb][acol+2][arow+64] = a1.z; As[nb][acol+3][arow+64] = a1.w;
            *(float4*)&Bs[nb][brow][bcol] = b0;
            *(float4*)&Bs[nb][brow+8][bcol] = b1;
            __syncthreads();
            buf = nb;
        }
    }

    const int crow = by * 128 + ty * 8;
    const int ccol = bx * 128 + tx * 8;
    float4 bz0 = *(const float4*)&bias[ccol];
    float4 bz1 = *(const float4*)&bias[ccol + 4];
#pragma unroll
    for (int i = 0; i < 8; ++i) {
        float4 o0 = make_float4(acc[i][0] + bz0.x, acc[i][1] + bz0.y,
                                acc[i][2] + bz0.z, acc[i][3] + bz0.w);
        float4 o1 = make_float4(acc[i][4] + bz1.x, acc[i][5] + bz1.y,
                                acc[i][6] + bz1.z, acc[i][7] + bz1.w);
        float* cp = C + (size_t)(crow + i) * N + ccol;
        *(float4*)cp = o0;
        *(float4*)(cp + 4) = o1;
    }
}

// ---------------------------------------------------------------------------
// RoPE + split qkv -> bf16 hi/lo Q,K,V in [H,S,HD]. Q pre-scaled by HD^-0.5.
// ---------------------------------------------------------------------------
__device__ __forceinline__ void bsplit(float x, __nv_bfloat16& h, __nv_bfloat16& l)
{
    h = __float2bfloat16_rn(x);
    l = __float2bfloat16_rn(x - __bfloat162float(h));
}

__global__ void rope_split_kernel(const float* __restrict__ fc)
{
    int idx = blockIdx.x * blockDim.x + threadIdx.x;
    const int total = SEQ * NH * (HD / 2);
    if (idx >= total) return;
    int i = idx & 63;
    int h = (idx >> 6) & 15;
    int s = idx >> 10;
    float c  = fc[(s * 64 + i) * 2 + 0];
    float sn = fc[(s * 64 + i) * 2 + 1];
    const float* row = g_qkv + (size_t)s * QKVN;
    int d = h * HD + 2 * i;
    float q0 = row[d],           q1 = row[d + 1];
    float k0 = row[DM + d],      k1 = row[DM + d + 1];
    float v0 = row[2 * DM + d],  v1 = row[2 * DM + d + 1];
    const float qs = 0.08838834764831845f;   // 128^-0.5
    float qr0 = (q0 * c - q1 * sn) * qs;
    float qr1 = (q1 * c + q0 * sn) * qs;
    float kr0 = k0 * c - k1 * sn;
    float kr1 = k1 * c + k0 * sn;

    size_t o = ((size_t)h * SEQ + s) * HD + 2 * i;
    __nv_bfloat16 h0, l0, h1, l1;

    bsplit(qr0, h0, l0); bsplit(qr1, h1, l1);
    *(__nv_bfloat162*)&g_qh[o] = __nv_bfloat162(h0, h1);
    *(__nv_bfloat162*)&g_ql[o] = __nv_bfloat162(l0, l1);

    bsplit(kr0, h0, l0); bsplit(kr1, h1, l1);
    *(__nv_bfloat162*)&g_kh[o] = __nv_bfloat162(h0, h1);
    *(__nv_bfloat162*)&g_kl[o] = __nv_bfloat162(l0, l1);

    bsplit(v0, h0, l0); bsplit(v1, h1, l1);
    *(__nv_bfloat162*)&g_vh[o] = __nv_bfloat162(h0, h1);
    *(__nv_bfloat162*)&g_vl[o] = __nv_bfloat162(l0, l1);
}

// ---------------------------------------------------------------------------
// Tensor-core flash attention (bf16 hi/lo split, fp32 softmax/accum).
// BM=128 q rows, BN=64 kv per iter, 8 warps (16 q rows each).
// Each CTA runs TWO q-tiles: (15-bx) then (bx) -> 34 iters per CTA, 128 CTAs.
// ---------------------------------------------------------------------------
#define FL_STRIDE 136   // bf16 elements per smem row (272B = 17*16B, conflict-free)
#define FL_Q_ELE  (128*FL_STRIDE)
#define FL_K_ELE  (64*FL_STRIDE)
#define FLASH_SMEM ((2*FL_Q_ELE + 4*FL_K_ELE) * 2)   // bytes = 139264

__device__ __forceinline__ void ldsm4(uint32_t& r0, uint32_t& r1, uint32_t& r2,
                                      uint32_t& r3, uint32_t addr)
{
    asm volatile("ldmatrix.sync.aligned.m8n8.x4.shared.b16 {%0,%1,%2,%3}, [%4];"
                 : "=r"(r0), "=r"(r1), "=r"(r2), "=r"(r3) : "r"(addr));
}
__device__ __forceinline__ void ldsm4t(uint32_t& r0, uint32_t& r1, uint32_t& r2,
                                       uint32_t& r3, uint32_t addr)
{
    asm volatile("ldmatrix.sync.aligned.m8n8.x4.trans.shared.b16 {%0,%1,%2,%3}, [%4];"
                 : "=r"(r0), "=r"(r1), "=r"(r2), "=r"(r3) : "r"(addr));
}
__device__ __forceinline__ void mma16816(float* c, uint32_t a0, uint32_t a1,
                                         uint32_t a2, uint32_t a3,
                                         uint32_t b0, uint32_t b1)
{
    asm volatile(
        "mma.sync.aligned.m16n8k16.row.col.f32.bf16.bf16.f32 "
        "{%0,%1,%2,%3}, {%4,%5,%6,%7}, {%8,%9}, {%0,%1,%2,%3};"
        : "+f"(c[0]), "+f"(c[1]), "+f"(c[2]), "+f"(c[3])
        : "r"(a0), "r"(a1), "r"(a2), "r"(a3), "r"(b0), "r"(b1));
}
// pack two fp32 into bf16x2 (x = low = first arg)
__device__ __forceinline__ uint32_t packbf(float x, float y)
{
    __nv_bfloat162 t = __floats2bfloat162_rn(x, y);
    return *reinterpret_cast<uint32_t*>(&t);
}
__device__ __forceinline__ void split2(float x0, float x1, uint32_t& h, uint32_t& l)
{
    float h0 = __bfloat162float(__float2bfloat16_rn(x0));
    float h1 = __bfloat162float(__float2bfloat16_rn(x1));
    h = packbf(h0, h1);
    l = packbf(x0 - h0, x1 - h1);
}

__global__ __launch_bounds__(256, 1)
void flash_attn_mma_kernel()
{
    extern __shared__ __nv_bfloat16 sm[];
    __nv_bfloat16* Qh = sm;
    __nv_bfloat16* Ql = Qh + FL_Q_ELE;
    __nv_bfloat16* Kh = Ql + FL_Q_ELE;
    __nv_bfloat16* Kl = Kh + FL_K_ELE;
    __nv_bfloat16* Vh = Kl + FL_K_ELE;
    __nv_bfloat16* Vl = Vh + FL_K_ELE;

    const int h    = blockIdx.y;
    const int tid  = threadIdx.x;
    const int warp = tid >> 5, lane = tid & 31;
    const int g = lane >> 3, ri = lane & 7;

    const __nv_bfloat16* gQh = g_qh + (size_t)h * SEQ * HD;
    const __nv_bfloat16* gQl = g_ql + (size_t)h * SEQ * HD;
    const __nv_bfloat16* gKh = g_kh + (size_t)h * SEQ * HD;
    const __nv_bfloat16* gKl = g_kl + (size_t)h * SEQ * HD;
    const __nv_bfloat16* gVh = g_vh + (size_t)h * SEQ * HD;
    const __nv_bfloat16* gVl = g_vl + (size_t)h * SEQ * HD;

    // shared-state base addresses (u32 shared space)
    const uint32_t sQh = (uint32_t)__cvta_generic_to_shared(Qh);
    const uint32_t sQl = (uint32_t)__cvta_generic_to_shared(Ql);
    const uint32_t sKh = (uint32_t)__cvta_generic_to_shared(Kh);
    const uint32_t sKl = (uint32_t)__cvta_generic_to_shared(Kl);
    const uint32_t sVh = (uint32_t)__cvta_generic_to_shared(Vh);
    const uint32_t sVl = (uint32_t)__cvta_generic_to_shared(Vl);

    // ldmatrix lane->address offsets
    // A (Q, non-trans): rows warp*16 + ri + (g&1)*8, col (g>>1)*8  (+32B per kchunk)
    const uint32_t aQoff = (uint32_t)(((warp*16 + ri + (g&1)*8) * FL_STRIDE + (g>>1)*8) * 2);
    // B (K, non-trans): rows ri + (g>>1)*8 (+16 per np), col (g&1)*8 (+32B per kchunk)
    const uint32_t bKoff = (uint32_t)(((ri + (g>>1)*8) * FL_STRIDE + (g&1)*8) * 2);
    // B (V, trans): rows ri + (g&1)*8 (+16 per kc2), col (g>>1)*8 (+16 elem per np)
    const uint32_t bVoff = (uint32_t)(((ri + (g&1)*8) * FL_STRIDE + (g>>1)*8) * 2);

    const int bx = blockIdx.x;

    for (int pass = 0; pass < 2; ++pass) {
        const int qt = pass ? bx : (15 - bx);

        __syncthreads();   // previous pass fully done before Q overwrite
        // load Q tile (hi+lo): 128 rows x 16 uint4 each
#pragma unroll
        for (int t = 0; t < 8; ++t) {
            int idx = tid + t * 256;
            int r = idx >> 4, c8 = (idx & 15) << 3;
            size_t gsrc = (size_t)(qt * 128 + r) * HD + c8;
            *(uint4*)&Qh[r * FL_STRIDE + c8] = *(const uint4*)&gQh[gsrc];
            *(uint4*)&Ql[r * FL_STRIDE + c8] = *(const uint4*)&gQl[gsrc];
        }

        float O[16][4];
        float m0 = -1e30f, m1 = -1e30f, l0 = 0.f, l1 = 0.f;
#pragma unroll
        for (int t = 0; t < 16; ++t)
#pragma unroll
            for (int c = 0; c < 4; ++c) O[t][c] = 0.f;

        const int jmax = 2 * qt + 1;
        for (int j = 0; j <= jmax; ++j) {
            __syncthreads();   // prior iter's V/K reads + Q stores fence
#pragma unroll
            for (int t = 0; t < 4; ++t) {
                int idx = tid + t * 256;
                int r = idx >> 4, c8 = (idx & 15) << 3;
                size_t gsrc = (size_t)(j * 64 + r) * HD + c8;
                *(uint4*)&Kh[r * FL_STRIDE + c8] = *(const uint4*)&gKh[gsrc];
                *(uint4*)&Kl[r * FL_STRIDE + c8] = *(const uint4*)&gKl[gsrc];
                *(uint4*)&Vh[r * FL_STRIDE + c8] = *(const uint4*)&gVh[gsrc];
                *(uint4*)&Vl[r * FL_STRIDE + c8] = *(const uint4*)&gVl[gsrc];
            }
            __syncthreads();

            // ---- S = Q K^T ----
            float S[8][4];
#pragma unroll
            for (int t = 0; t < 8; ++t)
#pragma unroll
                for (int c = 0; c < 4; ++c) S[t][c] = 0.f;

#pragma unroll
            for (int kc = 0; kc < 8; ++kc) {
                uint32_t qh0,qh1,qh2,qh3, ql0,ql1,ql2,ql3;
                ldsm4(qh0,qh1,qh2,qh3, sQh + aQoff + kc*32);
                ldsm4(ql0,ql1,ql2,ql3, sQl + aQoff + kc*32);
#pragma unroll
                for (int np = 0; np < 4; ++np) {
                    uint32_t kh0,kh1,kh2,kh3, kl0,kl1,kl2,kl3;
                    uint32_t o = bKoff + (uint32_t)(np*16*FL_STRIDE*2) + kc*32;
                    ldsm4(kh0,kh1,kh2,kh3, sKh + o);
                    ldsm4(kl0,kl1,kl2,kl3, sKl + o);
                    mma16816(S[2*np],   qh0,qh1,qh2,qh3, kh0,kh1);
                    mma16816(S[2*np],   ql0,ql1,ql2,ql3, kh0,kh1);
                    mma16816(S[2*np],   qh0,qh1,qh2,qh3, kl0,kl1);
                    mma16816(S[2*np+1], qh0,qh1,qh2,qh3, kh2,kh3);
                    mma16816(S[2*np+1], ql0,ql1,ql2,ql3, kh2,kh3);
                    mma16816(S[2*np+1], qh0,qh1,qh2,qh3, kl2,kl3);
                }
            }

            // ---- causal mask (only straddling tiles) ----
            const int row0 = qt * 128 + warp * 16 + (lane >> 2);
            if (j >= 2 * qt) {
#pragma unroll
                for (int t = 0; t < 8; ++t) {
                    int col = j * 64 + t * 8 + 2 * (lane & 3);
#pragma unroll
                    for (int c = 0; c < 4; ++c) {
                        int cc = col + (c & 1);
                        int rr = row0 + ((c >= 2) ? 8 : 0);
                        if (cc > rr) S[t][c] = -1e30f;
                    }
                }
            }

            // ---- online softmax ----
            float mx0 = -1e30f, mx1 = -1e30f;
#pragma unroll
            for (int t = 0; t < 8; ++t) {
                mx0 = fmaxf(mx0, fmaxf(S[t][0], S[t][1]));
                mx1 = fmaxf(mx1, fmaxf(S[t][2], S[t][3]));
            }
            mx0 = fmaxf(mx0, __shfl_xor_sync(0xffffffffu, mx0, 1));
            mx0 = fmaxf(mx0, __shfl_xor_sync(0xffffffffu, mx0, 2));
            mx1 = fmaxf(mx1, __shfl_xor_sync(0xffffffffu, mx1, 1));
            mx1 = fmaxf(mx1, __shfl_xor_sync(0xffffffffu, mx1, 2));
            float mn0 = fmaxf(m0, mx0), mn1 = fmaxf(m1, mx1);
            float al0 = __expf(m0 - mn0), al1 = __expf(m1 - mn1);
            float rs0 = 0.f, rs1 = 0.f;
#pragma unroll
            for (int t = 0; t < 8; ++t) {
                S[t][0] = __expf(S[t][0] - mn0);
                S[t][1] = __expf(S[t][1] - mn0);
                S[t][2] = __expf(S[t][2] - mn1);
                S[t][3] = __expf(S[t][3] - mn1);
                rs0 += S[t][0] + S[t][1];
                rs1 += S[t][2] + S[t][3];
            }
            rs0 += __shfl_xor_sync(0xffffffffu, rs0, 1);
            rs0 += __shfl_xor_sync(0xffffffffu, rs0, 2);
            rs1 += __shfl_xor_sync(0xffffffffu, rs1, 1);
            rs1 += __shfl_xor_sync(0xffffffffu, rs1, 2);
            l0 = l0 * al0 + rs0;  m0 = mn0;
            l1 = l1 * al1 + rs1;  m1 = mn1;
#pragma unroll
            for (int t = 0; t < 16; ++t) {
                O[t][0] *= al0; O[t][1] *= al0;
                O[t][2] *= al1; O[t][3] *= al1;
            }

            // ---- O += P V ----
#pragma unroll
            for (int kc2 = 0; kc2 < 4; ++kc2) {
                uint32_t ph0,ph1,ph2,ph3, pl0,pl1,pl2,pl3;
                split2(S[2*kc2][0],   S[2*kc2][1],   ph0, pl0);
                split2(S[2*kc2][2],   S[2*kc2][3],   ph1, pl1);
                split2(S[2*kc2+1][0], S[2*kc2+1][1], ph2, pl2);
                split2(S[2*kc2+1][2], S[2*kc2+1][3], ph3, pl3);
#pragma unroll
                for (int np = 0; np < 8; ++np) {
                    uint32_t vh0,vh1,vh2,vh3, vl0,vl1,vl2,vl3;
                    uint32_t o = bVoff + (uint32_t)(kc2*16*FL_STRIDE*2) + np*32;
                    ldsm4t(vh0,vh1,vh2,vh3, sVh + o);
                    ldsm4t(vl0,vl1,vl2,vl3, sVl + o);
                    mma16816(O[2*np],   ph0,ph1,ph2,ph3, vh0,vh1);
                    mma16816(O[2*np],   pl0,pl1,pl2,pl3, vh0,vh1);
                    mma16816(O[2*np],   ph0,ph1,ph2,ph3, vl0,vl1);
                    mma16816(O[2*np+1], ph0,ph1,ph2,ph3, vh2,vh3);
                    mma16816(O[2*np+1], pl0,pl1,pl2,pl3, vh2,vh3);
                    mma16816(O[2*np+1], ph0,ph1,ph2,ph3, vl2,vl3);
                }
            }
        }

        // ---- normalize + store ctx [S, D] (head h occupies cols h*128..) ----
        float inv0 = 1.f / l0, inv1 = 1.f / l1;
        int grow = qt * 128 + warp * 16 + (lane >> 2);
        float* base0 = g_ctx + (size_t)grow * DM + h * HD;
        float* base1 = base0 + (size_t)8 * DM;
#pragma unroll
        for (int t = 0; t < 16; ++t) {
            int c = t * 8 + 2 * (lane & 3);
            *(float2*)(base0 + c) = make_float2(O[t][0] * inv0, O[t][1] * inv0);
            *(float2*)(base1 + c) = make_float2(O[t][2] * inv1, O[t][3] * inv1);
        }
    }
}

// ---------------------------------------------------------------------------
extern "C" void kernel_launch(void* const* d_in, const int* in_sizes, int n_in,
                              void* d_out, int out_size)
{
    const float* x    = (const float*)d_in[0];
    const float* fc   = (const float*)d_in[1];
    // d_in[2] = input_pos (arange -> identity scatter, unused)
    const float* Wqkv = (const float*)d_in[3];
    const float* bqkv = (const float*)d_in[4];
    const float* Wd   = (const float*)d_in[5];
    const float* bd   = (const float*)d_in[6];
    float* out = (float*)d_out;

    float *qkv_p, *ctx_p;
    cudaGetSymbolAddress((void**)&qkv_p, g_qkv);
    cudaGetSymbolAddress((void**)&ctx_p, g_ctx);

    // 1) fused QKV projection: [S,D] @ [D,3D] + bias
    sgemm_bias_kernel<<<dim3(QKVN / 128, SEQ / 128), 256>>>(
        x, Wqkv, bqkv, qkv_p, SEQ, QKVN, DM);

    // 2) RoPE + bf16 hi/lo split into [H,S,HD] Q/K/V (Q pre-scaled)
    rope_split_kernel<<<(SEQ * NH * (HD / 2) + 255) / 256, 256>>>(fc);

    // 3) causal flash attention on tensor cores (paired q-tiles: 8 x 16 CTAs)
    cudaFuncSetAttribute(flash_attn_mma_kernel,
                         cudaFuncAttributeMaxDynamicSharedMemorySize, FLASH_SMEM);
    flash_attn_mma_kernel<<<dim3(8, NH), 256, FLASH_SMEM>>>();

    // 4) output projection: ctx @ Wdense + bias
    sgemm_bias_kernel<<<dim3(DM / 128, SEQ / 128), 256>>>(
        ctx_p, Wd, bd, out, SEQ, DM, DM);
}

// round 7
// speedup vs baseline: 3.1189x; 2.2607x over previous
#include <cuda_runtime.h>
#include <cuda_bf16.h>
#include <math.h>
#include <stdint.h>

#define SEQ 2048
#define DM 2048
#define NH 16
#define HD 128
#define QKVN (3*DM)

// Scratch (allocation-free rule: __device__ globals)
__device__ float g_qkv[SEQ * QKVN];     // [S, 3D]
// bf16 hi/lo split copies for tensor-core attention, [H][S][HD]
__device__ __nv_bfloat16 g_qh[NH*SEQ*HD], g_ql[NH*SEQ*HD];
__device__ __nv_bfloat16 g_kh[NH*SEQ*HD], g_kl[NH*SEQ*HD];
__device__ __nv_bfloat16 g_vh[NH*SEQ*HD], g_vl[NH*SEQ*HD];
// bf16 hi/lo splits for mma projection GEMMs
__device__ __nv_bfloat16 g_xh[SEQ*DM],   g_xl[SEQ*DM];     // A of QKV
__device__ __nv_bfloat16 g_wqh[DM*QKVN], g_wql[DM*QKVN];   // B of QKV
__device__ __nv_bfloat16 g_wdh[DM*DM],   g_wdl[DM*DM];     // B of dense
__device__ __nv_bfloat16 g_ch[SEQ*DM],   g_cl[SEQ*DM];     // A of dense (ctx)

// ---------------------------------------------------------------------------
// helpers
// ---------------------------------------------------------------------------
__device__ __forceinline__ void bsplit(float x, __nv_bfloat16& h, __nv_bfloat16& l)
{
    h = __float2bfloat16_rn(x);
    l = __float2bfloat16_rn(x - __bfloat162float(h));
}
__device__ __forceinline__ void ldsm4(uint32_t& r0, uint32_t& r1, uint32_t& r2,
                                      uint32_t& r3, uint32_t addr)
{
    asm volatile("ldmatrix.sync.aligned.m8n8.x4.shared.b16 {%0,%1,%2,%3}, [%4];"
                 : "=r"(r0), "=r"(r1), "=r"(r2), "=r"(r3) : "r"(addr));
}
__device__ __forceinline__ void ldsm4t(uint32_t& r0, uint32_t& r1, uint32_t& r2,
                                       uint32_t& r3, uint32_t addr)
{
    asm volatile("ldmatrix.sync.aligned.m8n8.x4.trans.shared.b16 {%0,%1,%2,%3}, [%4];"
                 : "=r"(r0), "=r"(r1), "=r"(r2), "=r"(r3) : "r"(addr));
}
__device__ __forceinline__ void mma16816(float* c, uint32_t a0, uint32_t a1,
                                         uint32_t a2, uint32_t a3,
                                         uint32_t b0, uint32_t b1)
{
    asm volatile(
        "mma.sync.aligned.m16n8k16.row.col.f32.bf16.bf16.f32 "
        "{%0,%1,%2,%3}, {%4,%5,%6,%7}, {%8,%9}, {%0,%1,%2,%3};"
        : "+f"(c[0]), "+f"(c[1]), "+f"(c[2]), "+f"(c[3])
        : "r"(a0), "r"(a1), "r"(a2), "r"(a3), "r"(b0), "r"(b1));
}
__device__ __forceinline__ uint32_t packbf(float x, float y)
{
    __nv_bfloat162 t = __floats2bfloat162_rn(x, y);
    return *reinterpret_cast<uint32_t*>(&t);
}
__device__ __forceinline__ void split2(float x0, float x1, uint32_t& h, uint32_t& l)
{
    float h0 = __bfloat162float(__float2bfloat16_rn(x0));
    float h1 = __bfloat162float(__float2bfloat16_rn(x1));
    h = packbf(h0, h1);
    l = packbf(x0 - h0, x1 - h1);
}

// ---------------------------------------------------------------------------
// presplit: fp32 -> bf16 hi/lo (element pairs)
// ---------------------------------------------------------------------------
__global__ void presplit_kernel(const float* __restrict__ src,
                                __nv_bfloat16* __restrict__ dh,
                                __nv_bfloat16* __restrict__ dl, int n2)
{
    int i = blockIdx.x * blockDim.x + threadIdx.x;
    if (i >= n2) return;
    float2 v = ((const float2*)src)[i];
    __nv_bfloat16 h0, l0, h1, l1;
    bsplit(v.x, h0, l0); bsplit(v.y, h1, l1);
    ((__nv_bfloat162*)dh)[i] = __nv_bfloat162(h0, h1);
    ((__nv_bfloat162*)dl)[i] = __nv_bfloat162(l0, l1);
}

// ---------------------------------------------------------------------------
// mma.sync bf16 hi/lo GEMM: C[M,N] = A[M,K]*B[K,N] + bias[N]
// CTA tile 128x128, K-step 32, 8 warps (warp tile 32x64), double-buffered.
// A smem [m][k] stride 40 (ldsm); B smem [k][n] stride 136 (ldsm.trans).
// ---------------------------------------------------------------------------
#define GA_STRIDE 40
#define GB_STRIDE 136
#define GA_BYTES  (128*GA_STRIDE*2)             // 10240
#define GB_BYTES  (32*GB_STRIDE*2)              // 8704
#define GBUF      (2*GA_BYTES + 2*GB_BYTES)     // 37888
#define GEMM_SMEM (2*GBUF)                      // 75776

__global__ __launch_bounds__(256)
void gemm_mma_kernel(const __nv_bfloat16* __restrict__ Ah,
                     const __nv_bfloat16* __restrict__ Al,
                     const __nv_bfloat16* __restrict__ Bh,
                     const __nv_bfloat16* __restrict__ Bl,
                     const float* __restrict__ bias,
                     float* __restrict__ C, int N, int K)
{
    extern __shared__ char gsm[];
    const int tid = threadIdx.x;
    const int warp = tid >> 5, lane = tid & 31;
    const int g = lane >> 3, ri = lane & 7;
    const int wm = warp & 3, wn = warp >> 2;
    const int m0 = blockIdx.y * 128, n0 = blockIdx.x * 128;

    // gmem load coords (per thread, 2 chunks each for A and B, hi+lo)
    const int a_r = tid >> 2, a_c = (tid & 3) << 3;   // rows +i*64
    const int b_r = tid >> 4, b_c = (tid & 15) << 3;  // rows +i*16

    const uint32_t sbase = (uint32_t)__cvta_generic_to_shared(gsm);

    float acc[2][8][4];
#pragma unroll
    for (int mf = 0; mf < 2; ++mf)
#pragma unroll
        for (int nf = 0; nf < 8; ++nf)
#pragma unroll
            for (int c = 0; c < 4; ++c) acc[mf][nf][c] = 0.f;

    uint4 ra_h[2], ra_l[2], rb_h[2], rb_l[2];

    const int nk = K >> 5;
    // prologue: load kt=0
#pragma unroll
    for (int i = 0; i < 2; ++i) {
        size_t ga = (size_t)(m0 + a_r + i * 64) * K + a_c;
        ra_h[i] = *(const uint4*)(Ah + ga);
        ra_l[i] = *(const uint4*)(Al + ga);
        size_t gb = (size_t)(b_r + i * 16) * N + n0 + b_c;
        rb_h[i] = *(const uint4*)(Bh + gb);
        rb_l[i] = *(const uint4*)(Bl + gb);
    }

    // ldmatrix offsets
    const uint32_t aoff = (uint32_t)(((wm*32 + ri + (g&1)*8) * GA_STRIDE + (g>>1)*8) * 2);
    const uint32_t boff = (uint32_t)(((ri + (g&1)*8) * GB_STRIDE + wn*64 + (g>>1)*8) * 2);

    for (int kt = 0; kt < nk; ++kt) {
        const int buf = kt & 1;
        {   // store staged regs -> smem[buf]
            char* base = gsm + buf * GBUF;
            __nv_bfloat16* pAh = (__nv_bfloat16*)(base);
            __nv_bfloat16* pAl = (__nv_bfloat16*)(base + GA_BYTES);
            __nv_bfloat16* pBh = (__nv_bfloat16*)(base + 2*GA_BYTES);
            __nv_bfloat16* pBl = (__nv_bfloat16*)(base + 2*GA_BYTES + GB_BYTES);
#pragma unroll
            for (int i = 0; i < 2; ++i) {
                *(uint4*)(pAh + (a_r + i*64) * GA_STRIDE + a_c) = ra_h[i];
                *(uint4*)(pAl + (a_r + i*64) * GA_STRIDE + a_c) = ra_l[i];
                *(uint4*)(pBh + (b_r + i*16) * GB_STRIDE + b_c) = rb_h[i];
                *(uint4*)(pBl + (b_r + i*16) * GB_STRIDE + b_c) = rb_l[i];
            }
        }
        __syncthreads();

        if (kt + 1 < nk) {   // prefetch next K-step
#pragma unroll
            for (int i = 0; i < 2; ++i) {
                size_t ga = (size_t)(m0 + a_r + i * 64) * K + (kt + 1) * 32 + a_c;
                ra_h[i] = *(const uint4*)(Ah + ga);
                ra_l[i] = *(const uint4*)(Al + ga);
                size_t gb = (size_t)((kt + 1) * 32 + b_r + i * 16) * N + n0 + b_c;
                rb_h[i] = *(const uint4*)(Bh + gb);
                rb_l[i] = *(const uint4*)(Bl + gb);
            }
        }

        const uint32_t sAh = sbase + buf * GBUF;
        const uint32_t sAl = sAh + GA_BYTES;
        const uint32_t sBh = sAh + 2*GA_BYTES;
        const uint32_t sBl = sBh + GB_BYTES;

#pragma unroll
        for (int k16 = 0; k16 < 2; ++k16) {
            uint32_t ah[2][4], al[2][4];
#pragma unroll
            for (int mf = 0; mf < 2; ++mf) {
                uint32_t o = aoff + (uint32_t)(mf * 16 * GA_STRIDE * 2) + k16 * 32;
                ldsm4(ah[mf][0], ah[mf][1], ah[mf][2], ah[mf][3], sAh + o);
                ldsm4(al[mf][0], al[mf][1], al[mf][2], al[mf][3], sAl + o);
            }
#pragma unroll
            for (int nfp = 0; nfp < 4; ++nfp) {
                uint32_t bh[4], bl[4];
                uint32_t o = boff + (uint32_t)(k16 * 16 * GB_STRIDE * 2) + nfp * 32;
                ldsm4t(bh[0], bh[1], bh[2], bh[3], sBh + o);
                ldsm4t(bl[0], bl[1], bl[2], bl[3], sBl + o);
#pragma unroll
                for (int mf = 0; mf < 2; ++mf) {
                    mma16816(acc[mf][2*nfp],   ah[mf][0],ah[mf][1],ah[mf][2],ah[mf][3], bh[0],bh[1]);
                    mma16816(acc[mf][2*nfp],   al[mf][0],al[mf][1],al[mf][2],al[mf][3], bh[0],bh[1]);
                    mma16816(acc[mf][2*nfp],   ah[mf][0],ah[mf][1],ah[mf][2],ah[mf][3], bl[0],bl[1]);
                    mma16816(acc[mf][2*nfp+1], ah[mf][0],ah[mf][1],ah[mf][2],ah[mf][3], bh[2],bh[3]);
                    mma16816(acc[mf][2*nfp+1], al[mf][0],al[mf][1],al[mf][2],al[mf][3], bh[2],bh[3]);
                    mma16816(acc[mf][2*nfp+1], ah[mf][0],ah[mf][1],ah[mf][2],ah[mf][3], bl[2],bl[3]);
                }
            }
        }
    }

    // epilogue: add bias, store fp32
#pragma unroll
    for (int mf = 0; mf < 2; ++mf) {
        int row = m0 + wm * 32 + mf * 16 + (lane >> 2);
#pragma unroll
        for (int nf = 0; nf < 8; ++nf) {
            int col = n0 + wn * 64 + nf * 8 + 2 * (lane & 3);
            float b0 = bias[col], b1 = bias[col + 1];
            *(float2*)(C + (size_t)row * N + col) =
                make_float2(acc[mf][nf][0] + b0, acc[mf][nf][1] + b1);
            *(float2*)(C + (size_t)(row + 8) * N + col) =
                make_float2(acc[mf][nf][2] + b0, acc[mf][nf][3] + b1);
        }
    }
}

// ---------------------------------------------------------------------------
// RoPE + split qkv -> bf16 hi/lo Q,K,V in [H,S,HD]. Q pre-scaled by HD^-0.5.
// ---------------------------------------------------------------------------
__global__ void rope_split_kernel(const float* __restrict__ fc)
{
    int idx = blockIdx.x * blockDim.x + threadIdx.x;
    const int total = SEQ * NH * (HD / 2);
    if (idx >= total) return;
    int i = idx & 63;
    int h = (idx >> 6) & 15;
    int s = idx >> 10;
    float c  = fc[(s * 64 + i) * 2 + 0];
    float sn = fc[(s * 64 + i) * 2 + 1];
    const float* row = g_qkv + (size_t)s * QKVN;
    int d = h * HD + 2 * i;
    float q0 = row[d],           q1 = row[d + 1];
    float k0 = row[DM + d],      k1 = row[DM + d + 1];
    float v0 = row[2 * DM + d],  v1 = row[2 * DM + d + 1];
    const float qs = 0.08838834764831845f;   // 128^-0.5
    float qr0 = (q0 * c - q1 * sn) * qs;
    float qr1 = (q1 * c + q0 * sn) * qs;
    float kr0 = k0 * c - k1 * sn;
    float kr1 = k1 * c + k0 * sn;

    size_t o = ((size_t)h * SEQ + s) * HD + 2 * i;
    __nv_bfloat16 h0, l0, h1, l1;

    bsplit(qr0, h0, l0); bsplit(qr1, h1, l1);
    *(__nv_bfloat162*)&g_qh[o] = __nv_bfloat162(h0, h1);
    *(__nv_bfloat162*)&g_ql[o] = __nv_bfloat162(l0, l1);

    bsplit(kr0, h0, l0); bsplit(kr1, h1, l1);
    *(__nv_bfloat162*)&g_kh[o] = __nv_bfloat162(h0, h1);
    *(__nv_bfloat162*)&g_kl[o] = __nv_bfloat162(l0, l1);

    bsplit(v0, h0, l0); bsplit(v1, h1, l1);
    *(__nv_bfloat162*)&g_vh[o] = __nv_bfloat162(h0, h1);
    *(__nv_bfloat162*)&g_vl[o] = __nv_bfloat162(l0, l1);
}

// ---------------------------------------------------------------------------
// Tensor-core flash attention (bf16 hi/lo split, fp32 softmax/accum).
// Epilogue writes ctx directly as bf16 hi/lo (A of the dense GEMM).
// ---------------------------------------------------------------------------
#define FL_STRIDE 136
#define FL_Q_ELE  (128*FL_STRIDE)
#define FL_K_ELE  (64*FL_STRIDE)
#define FLASH_SMEM ((2*FL_Q_ELE + 4*FL_K_ELE) * 2)

__global__ __launch_bounds__(256, 1)
void flash_attn_mma_kernel()
{
    extern __shared__ __nv_bfloat16 sm[];
    __nv_bfloat16* Qh = sm;
    __nv_bfloat16* Ql = Qh + FL_Q_ELE;
    __nv_bfloat16* Kh = Ql + FL_Q_ELE;
    __nv_bfloat16* Kl = Kh + FL_K_ELE;
    __nv_bfloat16* Vh = Kl + FL_K_ELE;
    __nv_bfloat16* Vl = Vh + FL_K_ELE;

    const int h    = blockIdx.y;
    const int tid  = threadIdx.x;
    const int warp = tid >> 5, lane = tid & 31;
    const int g = lane >> 3, ri = lane & 7;

    const __nv_bfloat16* gQh = g_qh + (size_t)h * SEQ * HD;
    const __nv_bfloat16* gQl = g_ql + (size_t)h * SEQ * HD;
    const __nv_bfloat16* gKh = g_kh + (size_t)h * SEQ * HD;
    const __nv_bfloat16* gKl = g_kl + (size_t)h * SEQ * HD;
    const __nv_bfloat16* gVh = g_vh + (size_t)h * SEQ * HD;
    const __nv_bfloat16* gVl = g_vl + (size_t)h * SEQ * HD;

    const uint32_t sQh = (uint32_t)__cvta_generic_to_shared(Qh);
    const uint32_t sQl = (uint32_t)__cvta_generic_to_shared(Ql);
    const uint32_t sKh = (uint32_t)__cvta_generic_to_shared(Kh);
    const uint32_t sKl = (uint32_t)__cvta_generic_to_shared(Kl);
    const uint32_t sVh = (uint32_t)__cvta_generic_to_shared(Vh);
    const uint32_t sVl = (uint32_t)__cvta_generic_to_shared(Vl);

    const uint32_t aQoff = (uint32_t)(((warp*16 + ri + (g&1)*8) * FL_STRIDE + (g>>1)*8) * 2);
    const uint32_t bKoff = (uint32_t)(((ri + (g>>1)*8) * FL_STRIDE + (g&1)*8) * 2);
    const uint32_t bVoff = (uint32_t)(((ri + (g&1)*8) * FL_STRIDE + (g>>1)*8) * 2);

    const int bx = blockIdx.x;

    for (int pass = 0; pass < 2; ++pass) {
        const int qt = pass ? bx : (15 - bx);

        __syncthreads();
#pragma unroll
        for (int t = 0; t < 8; ++t) {
            int idx = tid + t * 256;
            int r = idx >> 4, c8 = (idx & 15) << 3;
            size_t gsrc = (size_t)(qt * 128 + r) * HD + c8;
            *(uint4*)&Qh[r * FL_STRIDE + c8] = *(const uint4*)&gQh[gsrc];
            *(uint4*)&Ql[r * FL_STRIDE + c8] = *(const uint4*)&gQl[gsrc];
        }

        float O[16][4];
        float m0 = -1e30f, m1 = -1e30f, l0 = 0.f, l1 = 0.f;
#pragma unroll
        for (int t = 0; t < 16; ++t)
#pragma unroll
            for (int c = 0; c < 4; ++c) O[t][c] = 0.f;

        const int jmax = 2 * qt + 1;
        for (int j = 0; j <= jmax; ++j) {
            __syncthreads();
#pragma unroll
            for (int t = 0; t < 4; ++t) {
                int idx = tid + t * 256;
                int r = idx >> 4, c8 = (idx & 15) << 3;
                size_t gsrc = (size_t)(j * 64 + r) * HD + c8;
                *(uint4*)&Kh[r * FL_STRIDE + c8] = *(const uint4*)&gKh[gsrc];
                *(uint4*)&Kl[r * FL_STRIDE + c8] = *(const uint4*)&gKl[gsrc];
                *(uint4*)&Vh[r * FL_STRIDE + c8] = *(const uint4*)&gVh[gsrc];
                *(uint4*)&Vl[r * FL_STRIDE + c8] = *(const uint4*)&gVl[gsrc];
            }
            __syncthreads();

            float S[8][4];
#pragma unroll
            for (int t = 0; t < 8; ++t)
#pragma unroll
                for (int c = 0; c < 4; ++c) S[t][c] = 0.f;

#pragma unroll
            for (int kc = 0; kc < 8; ++kc) {
                uint32_t qh0,qh1,qh2,qh3, ql0,ql1,ql2,ql3;
                ldsm4(qh0,qh1,qh2,qh3, sQh + aQoff + kc*32);
                ldsm4(ql0,ql1,ql2,ql3, sQl + aQoff + kc*32);
#pragma unroll
                for (int np = 0; np < 4; ++np) {
                    uint32_t kh0,kh1,kh2,kh3, kl0,kl1,kl2,kl3;
                    uint32_t o = bKoff + (uint32_t)(np*16*FL_STRIDE*2) + kc*32;
                    ldsm4(kh0,kh1,kh2,kh3, sKh + o);
                    ldsm4(kl0,kl1,kl2,kl3, sKl + o);
                    mma16816(S[2*np],   qh0,qh1,qh2,qh3, kh0,kh1);
                    mma16816(S[2*np],   ql0,ql1,ql2,ql3, kh0,kh1);
                    mma16816(S[2*np],   qh0,qh1,qh2,qh3, kl0,kl1);
                    mma16816(S[2*np+1], qh0,qh1,qh2,qh3, kh2,kh3);
                    mma16816(S[2*np+1], ql0,ql1,ql2,ql3, kh2,kh3);
                    mma16816(S[2*np+1], qh0,qh1,qh2,qh3, kl2,kl3);
                }
            }

            const int row0 = qt * 128 + warp * 16 + (lane >> 2);
            if (j >= 2 * qt) {
#pragma unroll
                for (int t = 0; t < 8; ++t) {
                    int col = j * 64 + t * 8 + 2 * (lane & 3);
#pragma unroll
                    for (int c = 0; c < 4; ++c) {
                        int cc = col + (c & 1);
                        int rr = row0 + ((c >= 2) ? 8 : 0);
                        if (cc > rr) S[t][c] = -1e30f;
                    }
                }
            }

            float mx0 = -1e30f, mx1 = -1e30f;
#pragma unroll
            for (int t = 0; t < 8; ++t) {
                mx0 = fmaxf(mx0, fmaxf(S[t][0], S[t][1]));
                mx1 = fmaxf(mx1, fmaxf(S[t][2], S[t][3]));
            }
            mx0 = fmaxf(mx0, __shfl_xor_sync(0xffffffffu, mx0, 1));
            mx0 = fmaxf(mx0, __shfl_xor_sync(0xffffffffu, mx0, 2));
            mx1 = fmaxf(mx1, __shfl_xor_sync(0xffffffffu, mx1, 1));
            mx1 = fmaxf(mx1, __shfl_xor_sync(0xffffffffu, mx1, 2));
            float mn0 = fmaxf(m0, mx0), mn1 = fmaxf(m1, mx1);
            float al0 = __expf(m0 - mn0), al1 = __expf(m1 - mn1);
            float rs0 = 0.f, rs1 = 0.f;
#pragma unroll
            for (int t = 0; t < 8; ++t) {
                S[t][0] = __expf(S[t][0] - mn0);
                S[t][1] = __expf(S[t][1] - mn0);
                S[t][2] = __expf(S[t][2] - mn1);
                S[t][3] = __expf(S[t][3] - mn1);
                rs0 += S[t][0] + S[t][1];
                rs1 += S[t][2] + S[t][3];
            }
            rs0 += __shfl_xor_sync(0xffffffffu, rs0, 1);
            rs0 += __shfl_xor_sync(0xffffffffu, rs0, 2);
            rs1 += __shfl_xor_sync(0xffffffffu, rs1, 1);
            rs1 += __shfl_xor_sync(0xffffffffu, rs1, 2);
            l0 = l0 * al0 + rs0;  m0 = mn0;
            l1 = l1 * al1 + rs1;  m1 = mn1;
#pragma unroll
            for (int t = 0; t < 16; ++t) {
                O[t][0] *= al0; O[t][1] *= al0;
                O[t][2] *= al1; O[t][3] *= al1;
            }

#pragma unroll
            for (int kc2 = 0; kc2 < 4; ++kc2) {
                uint32_t ph0,ph1,ph2,ph3, pl0,pl1,pl2,pl3;
                split2(S[2*kc2][0],   S[2*kc2][1],   ph0, pl0);
                split2(S[2*kc2][2],   S[2*kc2][3],   ph1, pl1);
                split2(S[2*kc2+1][0], S[2*kc2+1][1], ph2, pl2);
                split2(S[2*kc2+1][2], S[2*kc2+1][3], ph3, pl3);
#pragma unroll
                for (int np = 0; np < 8; ++np) {
                    uint32_t vh0,vh1,vh2,vh3, vl0,vl1,vl2,vl3;
                    uint32_t o = bVoff + (uint32_t)(kc2*16*FL_STRIDE*2) + np*32;
                    ldsm4t(vh0,vh1,vh2,vh3, sVh + o);
                    ldsm4t(vl0,vl1,vl2,vl3, sVl + o);
                    mma16816(O[2*np],   ph0,ph1,ph2,ph3, vh0,vh1);
                    mma16816(O[2*np],   pl0,pl1,pl2,pl3, vh0,vh1);
                    mma16816(O[2*np],   ph0,ph1,ph2,ph3, vl0,vl1);
                    mma16816(O[2*np+1], ph0,ph1,ph2,ph3, vh2,vh3);
                    mma16816(O[2*np+1], pl0,pl1,pl2,pl3, vh2,vh3);
                    mma16816(O[2*np+1], ph0,ph1,ph2,ph3, vl2,vl3);
                }
            }
        }

        // normalize + store ctx as bf16 hi/lo, [S, D] layout (head h cols)
        float inv0 = 1.f / l0, inv1 = 1.f / l1;
        int grow = qt * 128 + warp * 16 + (lane >> 2);
        size_t off0 = (size_t)grow * DM + h * HD;
        size_t off1 = off0 + (size_t)8 * DM;
#pragma unroll
        for (int t = 0; t < 16; ++t) {
            int c = t * 8 + 2 * (lane & 3);
            uint32_t hh, ll;
            split2(O[t][0] * inv0, O[t][1] * inv0, hh, ll);
            *(uint32_t*)&g_ch[off0 + c] = hh;
            *(uint32_t*)&g_cl[off0 + c] = ll;
            split2(O[t][2] * inv1, O[t][3] * inv1, hh, ll);
            *(uint32_t*)&g_ch[off1 + c] = hh;
            *(uint32_t*)&g_cl[off1 + c] = ll;
        }
    }
}

// ---------------------------------------------------------------------------
extern "C" void kernel_launch(void* const* d_in, const int* in_sizes, int n_in,
                              void* d_out, int out_size)
{
    const float* x    = (const float*)d_in[0];
    const float* fc   = (const float*)d_in[1];
    // d_in[2] = input_pos (arange -> identity scatter, unused)
    const float* Wqkv = (const float*)d_in[3];
    const float* bqkv = (const float*)d_in[4];
    const float* Wd   = (const float*)d_in[5];
    const float* bd   = (const float*)d_in[6];
    float* out = (float*)d_out;

    float* qkv_p;
    cudaGetSymbolAddress((void**)&qkv_p, g_qkv);
    __nv_bfloat16 *xh, *xl, *wqh, *wql, *wdh, *wdl, *ch, *cl;
    cudaGetSymbolAddress((void**)&xh,  g_xh);  cudaGetSymbolAddress((void**)&xl,  g_xl);
    cudaGetSymbolAddress((void**)&wqh, g_wqh); cudaGetSymbolAddress((void**)&wql, g_wql);
    cudaGetSymbolAddress((void**)&wdh, g_wdh); cudaGetSymbolAddress((void**)&wdl, g_wdl);
    cudaGetSymbolAddress((void**)&ch,  g_ch);  cudaGetSymbolAddress((void**)&cl,  g_cl);

    cudaFuncSetAttribute(gemm_mma_kernel,
                         cudaFuncAttributeMaxDynamicSharedMemorySize, GEMM_SMEM);
    cudaFuncSetAttribute(flash_attn_mma_kernel,
                         cudaFuncAttributeMaxDynamicSharedMemorySize, FLASH_SMEM);

    // 0) presplit inputs to bf16 hi/lo
    presplit_kernel<<<(SEQ*DM/2 + 255)/256, 256>>>(x, xh, xl, SEQ*DM/2);
    presplit_kernel<<<(DM*QKVN/2 + 255)/256, 256>>>(Wqkv, wqh, wql, DM*QKVN/2);
    presplit_kernel<<<(DM*DM/2 + 255)/256, 256>>>(Wd, wdh, wdl, DM*DM/2);

    // 1) QKV projection (mma.sync): [S,D] @ [D,3D] + bias
    gemm_mma_kernel<<<dim3(QKVN/128, SEQ/128), 256, GEMM_SMEM>>>(
        xh, xl, wqh, wql, bqkv, qkv_p, QKVN, DM);

    // 2) RoPE + bf16 hi/lo split into [H,S,HD] Q/K/V (Q pre-scaled)
    rope_split_kernel<<<(SEQ * NH * (HD / 2) + 255) / 256, 256>>>(fc);

    // 3) causal flash attention (paired q-tiles: 8 x 16 CTAs); writes ctx hi/lo
    flash_attn_mma_kernel<<<dim3(8, NH), 256, FLASH_SMEM>>>();

    // 4) output projection (mma.sync): ctx @ Wdense + bias
    gemm_mma_kernel<<<dim3(DM/128, SEQ/128), 256, GEMM_SMEM>>>(
        ch, cl, wdh, wdl, bd, out, DM, DM);
}

// round 8
// speedup vs baseline: 3.1427x; 1.0076x over previous
#include <cuda_runtime.h>
#include <cuda_bf16.h>
#include <math.h>
#include <stdint.h>

#define SEQ 2048
#define DM 2048
#define NH 16
#define HD 128
#define QKVN (3*DM)

// Scratch (allocation-free rule: __device__ globals)
__device__ float g_qkv[SEQ * QKVN];     // [S, 3D]
// bf16 hi/lo split copies for tensor-core attention, [H][S][HD]
__device__ __nv_bfloat16 g_qh[NH*SEQ*HD], g_ql[NH*SEQ*HD];
__device__ __nv_bfloat16 g_kh[NH*SEQ*HD], g_kl[NH*SEQ*HD];
__device__ __nv_bfloat16 g_vh[NH*SEQ*HD], g_vl[NH*SEQ*HD];
// bf16 hi/lo splits for mma projection GEMMs
__device__ __nv_bfloat16 g_xh[SEQ*DM],   g_xl[SEQ*DM];     // A of QKV
__device__ __nv_bfloat16 g_wqh[DM*QKVN], g_wql[DM*QKVN];   // B of QKV
__device__ __nv_bfloat16 g_wdh[DM*DM],   g_wdl[DM*DM];     // B of dense
__device__ __nv_bfloat16 g_ch[SEQ*DM],   g_cl[SEQ*DM];     // A of dense (ctx)

// ---------------------------------------------------------------------------
// helpers
// ---------------------------------------------------------------------------
__device__ __forceinline__ void bsplit(float x, __nv_bfloat16& h, __nv_bfloat16& l)
{
    h = __float2bfloat16_rn(x);
    l = __float2bfloat16_rn(x - __bfloat162float(h));
}
__device__ __forceinline__ void ldsm4(uint32_t& r0, uint32_t& r1, uint32_t& r2,
                                      uint32_t& r3, uint32_t addr)
{
    asm volatile("ldmatrix.sync.aligned.m8n8.x4.shared.b16 {%0,%1,%2,%3}, [%4];"
                 : "=r"(r0), "=r"(r1), "=r"(r2), "=r"(r3) : "r"(addr));
}
__device__ __forceinline__ void ldsm4t(uint32_t& r0, uint32_t& r1, uint32_t& r2,
                                       uint32_t& r3, uint32_t addr)
{
    asm volatile("ldmatrix.sync.aligned.m8n8.x4.trans.shared.b16 {%0,%1,%2,%3}, [%4];"
                 : "=r"(r0), "=r"(r1), "=r"(r2), "=r"(r3) : "r"(addr));
}
__device__ __forceinline__ void mma16816(float* c, uint32_t a0, uint32_t a1,
                                         uint32_t a2, uint32_t a3,
                                         uint32_t b0, uint32_t b1)
{
    asm volatile(
        "mma.sync.aligned.m16n8k16.row.col.f32.bf16.bf16.f32 "
        "{%0,%1,%2,%3}, {%4,%5,%6,%7}, {%8,%9}, {%0,%1,%2,%3};"
        : "+f"(c[0]), "+f"(c[1]), "+f"(c[2]), "+f"(c[3])
        : "r"(a0), "r"(a1), "r"(a2), "r"(a3), "r"(b0), "r"(b1));
}
__device__ __forceinline__ uint32_t packbf(float x, float y)
{
    __nv_bfloat162 t = __floats2bfloat162_rn(x, y);
    return *reinterpret_cast<uint32_t*>(&t);
}
__device__ __forceinline__ void split2(float x0, float x1, uint32_t& h, uint32_t& l)
{
    float h0 = __bfloat162float(__float2bfloat16_rn(x0));
    float h1 = __bfloat162float(__float2bfloat16_rn(x1));
    h = packbf(h0, h1);
    l = packbf(x0 - h0, x1 - h1);
}
__device__ __forceinline__ void cpa16(uint32_t saddr, const void* gaddr)
{
    asm volatile("cp.async.cg.shared.global [%0], [%1], 16;"
                 :: "r"(saddr), "l"(gaddr));
}
__device__ __forceinline__ void cpa_commit()
{
    asm volatile("cp.async.commit_group;" ::: "memory");
}
template <int N>
__device__ __forceinline__ void cpa_wait()
{
    asm volatile("cp.async.wait_group %0;" :: "n"(N) : "memory");
}

// ---------------------------------------------------------------------------
// presplit: fp32 -> bf16 hi/lo (element pairs)
// ---------------------------------------------------------------------------
__global__ void presplit_kernel(const float* __restrict__ src,
                                __nv_bfloat16* __restrict__ dh,
                                __nv_bfloat16* __restrict__ dl, int n2)
{
    int i = blockIdx.x * blockDim.x + threadIdx.x;
    if (i >= n2) return;
    float2 v = ((const float2*)src)[i];
    __nv_bfloat16 h0, l0, h1, l1;
    bsplit(v.x, h0, l0); bsplit(v.y, h1, l1);
    ((__nv_bfloat162*)dh)[i] = __nv_bfloat162(h0, h1);
    ((__nv_bfloat162*)dl)[i] = __nv_bfloat162(l0, l1);
}

// ---------------------------------------------------------------------------
// mma.sync bf16 hi/lo GEMM: C[M,N] = A[M,K]*B[K,N] + bias[N]
// CTA tile 128x128, K-step 32, 8 warps (warp tile 32x64).
// cp.async double-buffered staging; 2 CTAs/SM.
// A smem [m][k] stride 40 (ldsm); B smem [k][n] stride 136 (ldsm.trans).
// ---------------------------------------------------------------------------
#define GA_STRIDE 40
#define GB_STRIDE 136
#define GA_BYTES  (128*GA_STRIDE*2)             // 10240
#define GB_BYTES  (32*GB_STRIDE*2)              // 8704
#define GBUF      (2*GA_BYTES + 2*GB_BYTES)     // 37888
#define GEMM_SMEM (2*GBUF)                      // 75776

__global__ __launch_bounds__(256, 2)
void gemm_mma_kernel(const __nv_bfloat16* __restrict__ Ah,
                     const __nv_bfloat16* __restrict__ Al,
                     const __nv_bfloat16* __restrict__ Bh,
                     const __nv_bfloat16* __restrict__ Bl,
                     const float* __restrict__ bias,
                     float* __restrict__ C, int N, int K)
{
    extern __shared__ char gsm[];
    const int tid = threadIdx.x;
    const int warp = tid >> 5, lane = tid & 31;
    const int g = lane >> 3, ri = lane & 7;
    const int wm = warp & 3, wn = warp >> 2;
    const int m0 = blockIdx.y * 128, n0 = blockIdx.x * 128;

    // gmem/smem staging coords (per thread, 2 chunks each for A and B, hi+lo)
    const int a_r = tid >> 2, a_c = (tid & 3) << 3;   // rows +i*64
    const int b_r = tid >> 4, b_c = (tid & 15) << 3;  // rows +i*16

    const uint32_t sbase = (uint32_t)__cvta_generic_to_shared(gsm);
    const int nk = K >> 5;

    // stage tile kt into buffer buf via cp.async (8 x 16B per thread)
    auto load_tile = [&](int kt, int buf) {
        const uint32_t bb = sbase + buf * GBUF;
#pragma unroll
        for (int i = 0; i < 2; ++i) {
            size_t ga = (size_t)(m0 + a_r + i * 64) * K + kt * 32 + a_c;
            uint32_t sa = bb + (uint32_t)(((a_r + i*64) * GA_STRIDE + a_c) * 2);
            cpa16(sa,            Ah + ga);
            cpa16(sa + GA_BYTES, Al + ga);
            size_t gb = (size_t)(kt * 32 + b_r + i * 16) * N + n0 + b_c;
            uint32_t sb = bb + 2*GA_BYTES + (uint32_t)(((b_r + i*16) * GB_STRIDE + b_c) * 2);
            cpa16(sb,            Bh + gb);
            cpa16(sb + GB_BYTES, Bl + gb);
        }
        cpa_commit();
    };

    float acc[2][8][4];
#pragma unroll
    for (int mf = 0; mf < 2; ++mf)
#pragma unroll
        for (int nf = 0; nf < 8; ++nf)
#pragma unroll
            for (int c = 0; c < 4; ++c) acc[mf][nf][c] = 0.f;

    // ldmatrix offsets
    const uint32_t aoff = (uint32_t)(((wm*32 + ri + (g&1)*8) * GA_STRIDE + (g>>1)*8) * 2);
    const uint32_t boff = (uint32_t)(((ri + (g&1)*8) * GB_STRIDE + wn*64 + (g>>1)*8) * 2);

    // prologue: fill both buffers
    load_tile(0, 0);
    load_tile(1, 1);
    cpa_wait<1>();          // buffer 0 ready
    __syncthreads();

    for (int kt = 0; kt < nk; ++kt) {
        const int buf = kt & 1;
        const uint32_t sAh = sbase + buf * GBUF;
        const uint32_t sAl = sAh + GA_BYTES;
        const uint32_t sBh = sAh + 2*GA_BYTES;
        const uint32_t sBl = sBh + GB_BYTES;

#pragma unroll
        for (int k16 = 0; k16 < 2; ++k16) {
            uint32_t ah[2][4], al[2][4];
#pragma unroll
            for (int mf = 0; mf < 2; ++mf) {
                uint32_t o = aoff + (uint32_t)(mf * 16 * GA_STRIDE * 2) + k16 * 32;
                ldsm4(ah[mf][0], ah[mf][1], ah[mf][2], ah[mf][3], sAh + o);
                ldsm4(al[mf][0], al[mf][1], al[mf][2], al[mf][3], sAl + o);
            }
#pragma unroll
            for (int nfp = 0; nfp < 4; ++nfp) {
                uint32_t bh[4], bl[4];
                uint32_t o = boff + (uint32_t)(k16 * 16 * GB_STRIDE * 2) + nfp * 32;
                ldsm4t(bh[0], bh[1], bh[2], bh[3], sBh + o);
                ldsm4t(bl[0], bl[1], bl[2], bl[3], sBl + o);
#pragma unroll
                for (int mf = 0; mf < 2; ++mf) {
                    mma16816(acc[mf][2*nfp],   ah[mf][0],ah[mf][1],ah[mf][2],ah[mf][3], bh[0],bh[1]);
                    mma16816(acc[mf][2*nfp],   al[mf][0],al[mf][1],al[mf][2],al[mf][3], bh[0],bh[1]);
                    mma16816(acc[mf][2*nfp],   ah[mf][0],ah[mf][1],ah[mf][2],ah[mf][3], bl[0],bl[1]);
                    mma16816(acc[mf][2*nfp+1], ah[mf][0],ah[mf][1],ah[mf][2],ah[mf][3], bh[2],bh[3]);
                    mma16816(acc[mf][2*nfp+1], al[mf][0],al[mf][1],al[mf][2],al[mf][3], bh[2],bh[3]);
                    mma16816(acc[mf][2*nfp+1], ah[mf][0],ah[mf][1],ah[mf][2],ah[mf][3], bl[2],bl[3]);
                }
            }
        }

        __syncthreads();                       // done reading buf
        if (kt + 2 < nk) load_tile(kt + 2, buf);
        if (kt + 1 < nk) {
            cpa_wait<1>();                     // buf (kt+1)&1 ready
            __syncthreads();
        }
    }

    // epilogue: add bias, store fp32
#pragma unroll
    for (int mf = 0; mf < 2; ++mf) {
        int row = m0 + wm * 32 + mf * 16 + (lane >> 2);
#pragma unroll
        for (int nf = 0; nf < 8; ++nf) {
            int col = n0 + wn * 64 + nf * 8 + 2 * (lane & 3);
            float b0 = bias[col], b1 = bias[col + 1];
            *(float2*)(C + (size_t)row * N + col) =
                make_float2(acc[mf][nf][0] + b0, acc[mf][nf][1] + b1);
            *(float2*)(C + (size_t)(row + 8) * N + col) =
                make_float2(acc[mf][nf][2] + b0, acc[mf][nf][3] + b1);
        }
    }
}

// ---------------------------------------------------------------------------
// RoPE + split qkv -> bf16 hi/lo Q,K,V in [H,S,HD]. Q pre-scaled by HD^-0.5.
// ---------------------------------------------------------------------------
__global__ void rope_split_kernel(const float* __restrict__ fc)
{
    int idx = blockIdx.x * blockDim.x + threadIdx.x;
    const int total = SEQ * NH * (HD / 2);
    if (idx >= total) return;
    int i = idx & 63;
    int h = (idx >> 6) & 15;
    int s = idx >> 10;
    float c  = fc[(s * 64 + i) * 2 + 0];
    float sn = fc[(s * 64 + i) * 2 + 1];
    const float* row = g_qkv + (size_t)s * QKVN;
    int d = h * HD + 2 * i;
    float q0 = row[d],           q1 = row[d + 1];
    float k0 = row[DM + d],      k1 = row[DM + d + 1];
    float v0 = row[2 * DM + d],  v1 = row[2 * DM + d + 1];
    const float qs = 0.08838834764831845f;   // 128^-0.5
    float qr0 = (q0 * c - q1 * sn) * qs;
    float qr1 = (q1 * c + q0 * sn) * qs;
    float kr0 = k0 * c - k1 * sn;
    float kr1 = k1 * c + k0 * sn;

    size_t o = ((size_t)h * SEQ + s) * HD + 2 * i;
    __nv_bfloat16 h0, l0, h1, l1;

    bsplit(qr0, h0, l0); bsplit(qr1, h1, l1);
    *(__nv_bfloat162*)&g_qh[o] = __nv_bfloat162(h0, h1);
    *(__nv_bfloat162*)&g_ql[o] = __nv_bfloat162(l0, l1);

    bsplit(kr0, h0, l0); bsplit(kr1, h1, l1);
    *(__nv_bfloat162*)&g_kh[o] = __nv_bfloat162(h0, h1);
    *(__nv_bfloat162*)&g_kl[o] = __nv_bfloat162(l0, l1);

    bsplit(v0, h0, l0); bsplit(v1, h1, l1);
    *(__nv_bfloat162*)&g_vh[o] = __nv_bfloat162(h0, h1);
    *(__nv_bfloat162*)&g_vl[o] = __nv_bfloat162(l0, l1);
}

// ---------------------------------------------------------------------------
// Tensor-core flash attention (bf16 hi/lo split, fp32 softmax/accum).
// Epilogue writes ctx directly as bf16 hi/lo (A of the dense GEMM).
// ---------------------------------------------------------------------------
#define FL_STRIDE 136
#define FL_Q_ELE  (128*FL_STRIDE)
#define FL_K_ELE  (64*FL_STRIDE)
#define FLASH_SMEM ((2*FL_Q_ELE + 4*FL_K_ELE) * 2)

__global__ __launch_bounds__(256, 1)
void flash_attn_mma_kernel()
{
    extern __shared__ __nv_bfloat16 sm[];
    __nv_bfloat16* Qh = sm;
    __nv_bfloat16* Ql = Qh + FL_Q_ELE;
    __nv_bfloat16* Kh = Ql + FL_Q_ELE;
    __nv_bfloat16* Kl = Kh + FL_K_ELE;
    __nv_bfloat16* Vh = Kl + FL_K_ELE;
    __nv_bfloat16* Vl = Vh + FL_K_ELE;

    const int h    = blockIdx.y;
    const int tid  = threadIdx.x;
    const int warp = tid >> 5, lane = tid & 31;
    const int g = lane >> 3, ri = lane & 7;

    const __nv_bfloat16* gQh = g_qh + (size_t)h * SEQ * HD;
    const __nv_bfloat16* gQl = g_ql + (size_t)h * SEQ * HD;
    const __nv_bfloat16* gKh = g_kh + (size_t)h * SEQ * HD;
    const __nv_bfloat16* gKl = g_kl + (size_t)h * SEQ * HD;
    const __nv_bfloat16* gVh = g_vh + (size_t)h * SEQ * HD;
    const __nv_bfloat16* gVl = g_vl + (size_t)h * SEQ * HD;

    const uint32_t sQh = (uint32_t)__cvta_generic_to_shared(Qh);
    const uint32_t sQl = (uint32_t)__cvta_generic_to_shared(Ql);
    const uint32_t sKh = (uint32_t)__cvta_generic_to_shared(Kh);
    const uint32_t sKl = (uint32_t)__cvta_generic_to_shared(Kl);
    const uint32_t sVh = (uint32_t)__cvta_generic_to_shared(Vh);
    const uint32_t sVl = (uint32_t)__cvta_generic_to_shared(Vl);

    const uint32_t aQoff = (uint32_t)(((warp*16 + ri + (g&1)*8) * FL_STRIDE + (g>>1)*8) * 2);
    const uint32_t bKoff = (uint32_t)(((ri + (g>>1)*8) * FL_STRIDE + (g&1)*8) * 2);
    const uint32_t bVoff = (uint32_t)(((ri + (g&1)*8) * FL_STRIDE + (g>>1)*8) * 2);

    const int bx = blockIdx.x;

    for (int pass = 0; pass < 2; ++pass) {
        const int qt = pass ? bx : (15 - bx);

        __syncthreads();
#pragma unroll
        for (int t = 0; t < 8; ++t) {
            int idx = tid + t * 256;
            int r = idx >> 4, c8 = (idx & 15) << 3;
            size_t gsrc = (size_t)(qt * 128 + r) * HD + c8;
            *(uint4*)&Qh[r * FL_STRIDE + c8] = *(const uint4*)&gQh[gsrc];
            *(uint4*)&Ql[r * FL_STRIDE + c8] = *(const uint4*)&gQl[gsrc];
        }

        float O[16][4];
        float m0 = -1e30f, m1 = -1e30f, l0 = 0.f, l1 = 0.f;
#pragma unroll
        for (int t = 0; t < 16; ++t)
#pragma unroll
            for (int c = 0; c < 4; ++c) O[t][c] = 0.f;

        const int jmax = 2 * qt + 1;
        for (int j = 0; j <= jmax; ++j) {
            __syncthreads();
#pragma unroll
            for (int t = 0; t < 4; ++t) {
                int idx = tid + t * 256;
                int r = idx >> 4, c8 = (idx & 15) << 3;
                size_t gsrc = (size_t)(j * 64 + r) * HD + c8;
                *(uint4*)&Kh[r * FL_STRIDE + c8] = *(const uint4*)&gKh[gsrc];
                *(uint4*)&Kl[r * FL_STRIDE + c8] = *(const uint4*)&gKl[gsrc];
                *(uint4*)&Vh[r * FL_STRIDE + c8] = *(const uint4*)&gVh[gsrc];
                *(uint4*)&Vl[r * FL_STRIDE + c8] = *(const uint4*)&gVl[gsrc];
            }
            __syncthreads();

            float S[8][4];
#pragma unroll
            for (int t = 0; t < 8; ++t)
#pragma unroll
                for (int c = 0; c < 4; ++c) S[t][c] = 0.f;

#pragma unroll
            for (int kc = 0; kc < 8; ++kc) {
                uint32_t qh0,qh1,qh2,qh3, ql0,ql1,ql2,ql3;
                ldsm4(qh0,qh1,qh2,qh3, sQh + aQoff + kc*32);
                ldsm4(ql0,ql1,ql2,ql3, sQl + aQoff + kc*32);
#pragma unroll
                for (int np = 0; np < 4; ++np) {
                    uint32_t kh0,kh1,kh2,kh3, kl0,kl1,kl2,kl3;
                    uint32_t o = bKoff + (uint32_t)(np*16*FL_STRIDE*2) + kc*32;
                    ldsm4(kh0,kh1,kh2,kh3, sKh + o);
                    ldsm4(kl0,kl1,kl2,kl3, sKl + o);
                    mma16816(S[2*np],   qh0,qh1,qh2,qh3, kh0,kh1);
                    mma16816(S[2*np],   ql0,ql1,ql2,ql3, kh0,kh1);
                    mma16816(S[2*np],   qh0,qh1,qh2,qh3, kl0,kl1);
                    mma16816(S[2*np+1], qh0,qh1,qh2,qh3, kh2,kh3);
                    mma16816(S[2*np+1], ql0,ql1,ql2,ql3, kh2,kh3);
                    mma16816(S[2*np+1], qh0,qh1,qh2,qh3, kl2,kl3);
                }
            }

            const int row0 = qt * 128 + warp * 16 + (lane >> 2);
            if (j >= 2 * qt) {
#pragma unroll
                for (int t = 0; t < 8; ++t) {
                    int col = j * 64 + t * 8 + 2 * (lane & 3);
#pragma unroll
                    for (int c = 0; c < 4; ++c) {
                        int cc = col + (c & 1);
                        int rr = row0 + ((c >= 2) ? 8 : 0);
                        if (cc > rr) S[t][c] = -1e30f;
                    }
                }
            }

            float mx0 = -1e30f, mx1 = -1e30f;
#pragma unroll
            for (int t = 0; t < 8; ++t) {
                mx0 = fmaxf(mx0, fmaxf(S[t][0], S[t][1]));
                mx1 = fmaxf(mx1, fmaxf(S[t][2], S[t][3]));
            }
            mx0 = fmaxf(mx0, __shfl_xor_sync(0xffffffffu, mx0, 1));
            mx0 = fmaxf(mx0, __shfl_xor_sync(0xffffffffu, mx0, 2));
            mx1 = fmaxf(mx1, __shfl_xor_sync(0xffffffffu, mx1, 1));
            mx1 = fmaxf(mx1, __shfl_xor_sync(0xffffffffu, mx1, 2));
            float mn0 = fmaxf(m0, mx0), mn1 = fmaxf(m1, mx1);
            float al0 = __expf(m0 - mn0), al1 = __expf(m1 - mn1);
            float rs0 = 0.f, rs1 = 0.f;
#pragma unroll
            for (int t = 0; t < 8; ++t) {
                S[t][0] = __expf(S[t][0] - mn0);
                S[t][1] = __expf(S[t][1] - mn0);
                S[t][2] = __expf(S[t][2] - mn1);
                S[t][3] = __expf(S[t][3] - mn1);
                rs0 += S[t][0] + S[t][1];
                rs1 += S[t][2] + S[t][3];
            }
            rs0 += __shfl_xor_sync(0xffffffffu, rs0, 1);
            rs0 += __shfl_xor_sync(0xffffffffu, rs0, 2);
            rs1 += __shfl_xor_sync(0xffffffffu, rs1, 1);
            rs1 += __shfl_xor_sync(0xffffffffu, rs1, 2);
            l0 = l0 * al0 + rs0;  m0 = mn0;
            l1 = l1 * al1 + rs1;  m1 = mn1;
#pragma unroll
            for (int t = 0; t < 16; ++t) {
                O[t][0] *= al0; O[t][1] *= al0;
                O[t][2] *= al1; O[t][3] *= al1;
            }

#pragma unroll
            for (int kc2 = 0; kc2 < 4; ++kc2) {
                uint32_t ph0,ph1,ph2,ph3, pl0,pl1,pl2,pl3;
                split2(S[2*kc2][0],   S[2*kc2][1],   ph0, pl0);
                split2(S[2*kc2][2],   S[2*kc2][3],   ph1, pl1);
                split2(S[2*kc2+1][0], S[2*kc2+1][1], ph2, pl2);
                split2(S[2*kc2+1][2], S[2*kc2+1][3], ph3, pl3);
#pragma unroll
                for (int np = 0; np < 8; ++np) {
                    uint32_t vh0,vh1,vh2,vh3, vl0,vl1,vl2,vl3;
                    uint32_t o = bVoff + (uint32_t)(kc2*16*FL_STRIDE*2) + np*32;
                    ldsm4t(vh0,vh1,vh2,vh3, sVh + o);
                    ldsm4t(vl0,vl1,vl2,vl3, sVl + o);
                    mma16816(O[2*np],   ph0,ph1,ph2,ph3, vh0,vh1);
                    mma16816(O[2*np],   pl0,pl1,pl2,pl3, vh0,vh1);
                    mma16816(O[2*np],   ph0,ph1,ph2,ph3, vl0,vl1);
                    mma16816(O[2*np+1], ph0,ph1,ph2,ph3, vh2,vh3);
                    mma16816(O[2*np+1], pl0,pl1,pl2,pl3, vh2,vh3);
                    mma16816(O[2*np+1], ph0,ph1,ph2,ph3, vl2,vl3);
                }
            }
        }

        // normalize + store ctx as bf16 hi/lo, [S, D] layout (head h cols)
        float inv0 = 1.f / l0, inv1 = 1.f / l1;
        int grow = qt * 128 + warp * 16 + (lane >> 2);
        size_t off0 = (size_t)grow * DM + h * HD;
        size_t off1 = off0 + (size_t)8 * DM;
#pragma unroll
        for (int t = 0; t < 16; ++t) {
            int c = t * 8 + 2 * (lane & 3);
            uint32_t hh, ll;
            split2(O[t][0] * inv0, O[t][1] * inv0, hh, ll);
            *(uint32_t*)&g_ch[off0 + c] = hh;
            *(uint32_t*)&g_cl[off0 + c] = ll;
            split2(O[t][2] * inv1, O[t][3] * inv1, hh, ll);
            *(uint32_t*)&g_ch[off1 + c] = hh;
            *(uint32_t*)&g_cl[off1 + c] = ll;
        }
    }
}

// ---------------------------------------------------------------------------
extern "C" void kernel_launch(void* const* d_in, const int* in_sizes, int n_in,
                              void* d_out, int out_size)
{
    const float* x    = (const float*)d_in[0];
    const float* fc   = (const float*)d_in[1];
    // d_in[2] = input_pos (arange -> identity scatter, unused)
    const float* Wqkv = (const float*)d_in[3];
    const float* bqkv = (const float*)d_in[4];
    const float* Wd   = (const float*)d_in[5];
    const float* bd   = (const float*)d_in[6];
    float* out = (float*)d_out;

    float* qkv_p;
    cudaGetSymbolAddress((void**)&qkv_p, g_qkv);
    __nv_bfloat16 *xh, *xl, *wqh, *wql, *wdh, *wdl, *ch, *cl;
    cudaGetSymbolAddress((void**)&xh,  g_xh);  cudaGetSymbolAddress((void**)&xl,  g_xl);
    cudaGetSymbolAddress((void**)&wqh, g_wqh); cudaGetSymbolAddress((void**)&wql, g_wql);
    cudaGetSymbolAddress((void**)&wdh, g_wdh); cudaGetSymbolAddress((void**)&wdl, g_wdl);
    cudaGetSymbolAddress((void**)&ch,  g_ch);  cudaGetSymbolAddress((void**)&cl,  g_cl);

    cudaFuncSetAttribute(gemm_mma_kernel,
                         cudaFuncAttributeMaxDynamicSharedMemorySize, GEMM_SMEM);
    cudaFuncSetAttribute(flash_attn_mma_kernel,
                         cudaFuncAttributeMaxDynamicSharedMemorySize, FLASH_SMEM);

    // 0) presplit inputs to bf16 hi/lo
    presplit_kernel<<<(SEQ*DM/2 + 255)/256, 256>>>(x, xh, xl, SEQ*DM/2);
    presplit_kernel<<<(DM*QKVN/2 + 255)/256, 256>>>(Wqkv, wqh, wql, DM*QKVN/2);
    presplit_kernel<<<(DM*DM/2 + 255)/256, 256>>>(Wd, wdh, wdl, DM*DM/2);

    // 1) QKV projection (mma.sync): [S,D] @ [D,3D] + bias
    gemm_mma_kernel<<<dim3(QKVN/128, SEQ/128), 256, GEMM_SMEM>>>(
        xh, xl, wqh, wql, bqkv, qkv_p, QKVN, DM);

    // 2) RoPE + bf16 hi/lo split into [H,S,HD] Q/K/V (Q pre-scaled)
    rope_split_kernel<<<(SEQ * NH * (HD / 2) + 255) / 256, 256>>>(fc);

    // 3) causal flash attention (paired q-tiles: 8 x 16 CTAs); writes ctx hi/lo
    flash_attn_mma_kernel<<<dim3(8, NH), 256, FLASH_SMEM>>>();

    // 4) output projection (mma.sync): ctx @ Wdense + bias
    gemm_mma_kernel<<<dim3(DM/128, SEQ/128), 256, GEMM_SMEM>>>(
        ch, cl, wdh, wdl, bd, out, DM, DM);
}